// round 17
// baseline (speedup 1.0000x reference)
#include <cuda_runtime.h>
#include <cstdint>

#define BB 4
#define CC 512
#define KK 64
#define NN 1024
#define NT 32   // k2 n-tile
#define GRID_A 128
#define GRID_B 256

typedef unsigned long long ull;

// ---- scratch (static __device__, no allocations) ----
__device__ __align__(16) float g_inv[KK * CC];    // [k][c]
__device__ __align__(16) float g_inv2t[CC * KK];  // [c][k]
__device__ __align__(16) float g_m2t[CC * KK];    // [c][k]
__device__ __align__(16) float g_ck[KK];
__device__ __align__(16) float g_wpart[(NN / NT) * BB * KK];  // [(nb*BB+b)*KK+k]
__device__ __align__(16) float g_part[4 * BB * KK * CC];      // 4 n-splits

// barrier state (monotonic gen -> graph-replay safe)
__device__ unsigned g_cntA[4] = {0, 0, 0, 0};
__device__ unsigned g_masterA = 0;
__device__ unsigned g_genA = 0;
__device__ unsigned g_cntB[4] = {0, 0, 0, 0};
__device__ unsigned g_masterB = 0;
__device__ unsigned g_genB = 0;

// ---- f32x2 helpers ----
__device__ __forceinline__ ull pack2(float x, float y) {
    ull r; asm("mov.b64 %0, {%1,%2};" : "=l"(r) : "f"(x), "f"(y)); return r;
}
__device__ __forceinline__ ull fma2(ull a, ull b, ull c) {
    ull d; asm("fma.rn.f32x2 %0, %1, %2, %3;" : "=l"(d) : "l"(a), "l"(b), "l"(c)); return d;
}
__device__ __forceinline__ float2 unpack2(ull v) {
    float2 f; asm("mov.b64 {%0,%1}, %2;" : "=f"(f.x), "=f"(f.y) : "l"(v)); return f;
}

// ---- cp.async helpers ----
__device__ __forceinline__ void cp_async16(void* smem_dst, const void* gsrc) {
    unsigned sa = (unsigned)__cvta_generic_to_shared(smem_dst);
    asm volatile("cp.async.cg.shared.global [%0], [%1], 16;\n" :: "r"(sa), "l"(gsrc));
}
__device__ __forceinline__ void cp_commit() { asm volatile("cp.async.commit_group;\n"); }
template <int N>
__device__ __forceinline__ void cp_wait() { asm volatile("cp.async.wait_group %0;\n" :: "n"(N)); }

// ---- spread grid barrier: 4 sub-counters + master (all blocks resident) ----
__device__ __forceinline__ void grid_bar(unsigned* cnt, unsigned* master,
                                         unsigned* gen, int sub_target, int blk) {
    __syncthreads();
    if (threadIdx.x == 0) {
        const unsigned g0 = *(volatile unsigned*)gen;
        __threadfence();
        const int sub = blk & 3;
        if (atomicAdd(&cnt[sub], 1u) == (unsigned)(sub_target - 1)) {
            cnt[sub] = 0;
            __threadfence();
            if (atomicAdd(master, 1u) == 3u) {
                *master = 0;
                __threadfence();
                atomicAdd(gen, 1u);
            }
        }
        while (*(volatile unsigned*)gen == g0) { __nanosleep(20); }
        __threadfence();
    }
    __syncthreads();
}

// ==================================================================
// Kernel A: [prep | barrier | d2 GEMM + softmax]
// 128 blocks x 256 threads, ~39KB smem -> all co-resident wave 1.
// ==================================================================
__global__ __launch_bounds__(256) void kernelA(const float* __restrict__ x,
                                               const float* __restrict__ anchor,
                                               const float* __restrict__ sp,
                                               float* __restrict__ soft_out) {
    __shared__ __align__(16) float Wis[3][16 * 64];
    __shared__ __align__(16) float M2s[3][16 * 64];
    __shared__ __align__(16) float Xs[3][16 * NT];
    __shared__ float S[64 * 33];

    const int tid = threadIdx.x;
    const int blk = blockIdx.x;

    // ---- Phase 1: prep (blocks 0..63, one k-row each; proven k1 body) ----
    if (blk < 64) {
        const int k = blk;
        float cks = 0.f;
#pragma unroll
        for (int r = 0; r < CC / 256; r++) {
            const int c = tid + r * 256;
            const float s = 1.f / (1.f + __expf(-sp[k * CC + c]));
            const float inv = __fdividef(1.f, s + 1e-7f);
            const float inv2 = inv * inv;
            const float a = anchor[k * CC + c];
            g_inv[k * CC + c] = inv;
            g_inv2t[c * KK + k] = inv2;
            g_m2t[c * KK + k] = -2.f * a * inv2;
            cks += a * a * inv2;
        }
        float v = cks;
#pragma unroll
        for (int o = 16; o > 0; o >>= 1) v += __shfl_xor_sync(0xffffffffu, v, o);
        if ((tid & 31) == 0) S[tid >> 5] = v;
        __syncthreads();
        if (tid == 0) {
            float s = 0.f;
#pragma unroll
            for (int w = 0; w < 8; w++) s += S[w];
            g_ck[k] = s;
        }
    }
    grid_bar(g_cntA, &g_masterA, &g_genA, GRID_A / 4, blk);

    // ---- Phase 2: d2 GEMM + softmax (proven R12 body) ----
    {
        const int b = blk >> 5;
        const int nb = blk & 31;
        const int n0 = nb * NT;
        const int tk = tid >> 4;  // 0..15 -> k base tk*4
        const int tn = tid & 15;  // 0..15 -> n base tn*2

        const float* xb = x + (size_t)b * CC * NN;

        auto issue = [&](int chunk, int buf) {
            const int c0 = chunk * 16;
            cp_async16(&Wis[buf][tid * 4], g_inv2t + c0 * KK + tid * 4);
            cp_async16(&M2s[buf][tid * 4], g_m2t + c0 * KK + tid * 4);
            if (tid < 128) {
                const int cc = tid >> 3, nn4 = (tid & 7) * 4;
                cp_async16(&Xs[buf][cc * NT + nn4], xb + (size_t)(c0 + cc) * NN + n0 + nn4);
            }
            cp_commit();
        };

        ull acc[2][2];
#pragma unroll
        for (int i = 0; i < 2; i++)
#pragma unroll
            for (int j = 0; j < 2; j++) acc[i][j] = 0ull;

        issue(0, 0);
        issue(1, 1);
        for (int ch = 0; ch < 32; ch++) {
            cp_wait<1>();
            __syncthreads();
            const int buf = ch - (ch / 3) * 3;  // ch % 3
            const float* Wb = Wis[buf];
            const float* Mb = M2s[buf];
            const float* Xb = Xs[buf];
#pragma unroll
            for (int cc = 0; cc < 16; cc++) {
                const ulonglong2 wp = *reinterpret_cast<const ulonglong2*>(Wb + cc * 64 + tk * 4);
                const ulonglong2 mp = *reinterpret_cast<const ulonglong2*>(Mb + cc * 64 + tk * 4);
                const float2 xv = *reinterpret_cast<const float2*>(Xb + cc * NT + tn * 2);
                const ull xd0 = pack2(xv.x, xv.x);
                const ull xd1 = pack2(xv.y, xv.y);
                ull t;
                t = fma2(wp.x, xd0, mp.x); acc[0][0] = fma2(t, xd0, acc[0][0]);
                t = fma2(wp.x, xd1, mp.x); acc[0][1] = fma2(t, xd1, acc[0][1]);
                t = fma2(wp.y, xd0, mp.y); acc[1][0] = fma2(t, xd0, acc[1][0]);
                t = fma2(wp.y, xd1, mp.y); acc[1][1] = fma2(t, xd1, acc[1][1]);
            }
            if (ch + 2 < 32) {
                const int nb2 = (ch + 2) - ((ch + 2) / 3) * 3;
                issue(ch + 2, nb2);
            }
        }

        // logits -> S (pad 33)
        {
            const int k0 = tk * 4;
#pragma unroll
            for (int kp = 0; kp < 2; kp++)
#pragma unroll
                for (int j = 0; j < 2; j++) {
                    const float2 v = unpack2(acc[kp][j]);
                    const int kk = k0 + kp * 2;
                    const int n = tn * 2 + j;
                    S[kk * 33 + n] = -0.5f * (v.x + g_ck[kk]);
                    S[(kk + 1) * 33 + n] = -0.5f * (v.y + g_ck[kk + 1]);
                }
        }
        __syncthreads();

        // serial softmax per column (threads 0..31) — proven shape
        if (tid < NT) {
            const int n = tid;
            float m = -1e30f;
#pragma unroll
            for (int k = 0; k < KK; k++) m = fmaxf(m, S[k * 33 + n]);
            float s = 0.f;
#pragma unroll
            for (int k = 0; k < KK; k++) s += __expf(S[k * 33 + n] - m);
            const float invs = 1.f / s;
            float* outp = soft_out + (size_t)b * KK * NN + n0 + n;
#pragma unroll
            for (int k = 0; k < KK; k++) {
                const float p = __expf(S[k * 33 + n] - m) * invs;
                S[k * 33 + n] = p;
                outp[(size_t)k * NN] = p;
            }
        }
        __syncthreads();

        // per-block wsum partials (threads 0..63, one per k)
        if (tid < 64) {
            float s = 0.f;
#pragma unroll
            for (int n = 0; n < NT; n++) s += S[tid * 33 + n];
            g_wpart[(nb * BB + b) * KK + tid] = s;
        }
    }
}

// ==================================================================
// Kernel B: [num GEMM | barrier | epilogue]
// 256 blocks x 256 threads (~13KB smem, co-resident).
// ==================================================================
__global__ __launch_bounds__(256) void kernelB(const float* __restrict__ x,
                                               const float* __restrict__ anchor,
                                               const float* __restrict__ soft,
                                               float* __restrict__ nodes_out) {
    __shared__ __align__(16) float As[2][16 * 68];  // [nn][k], pad 68
    __shared__ __align__(16) float Xs[2][16 * 36];  // [nn][c-local], pad 36

    const int tid = threadIdx.x;
    const int blk = blockIdx.x;

    // ---- Phase 1: num GEMM (proven R12 body), 256 items ----
    {
        const int ct = blk & 15;
        const int b = (blk >> 4) & 3;
        const int ns = blk >> 6;
        const int c0 = ct * 32;
        const int nbeg = ns * (NN / 4);

        const int tc = tid & 15;   // c pair base = tc*2
        const int tk = tid >> 4;   // k base = tk*4 (two packed pairs)
        const int lrow = tid >> 4; // load row base (0..15)
        const int lnn = tid & 15;  // load nn

        ull acc[2][2];
#pragma unroll
        for (int i = 0; i < 2; i++) { acc[i][0] = 0ull; acc[i][1] = 0ull; }

        const float* Ab = soft + (size_t)b * KK * NN;
        const float* xb = x + (size_t)b * CC * NN;

        // prologue: load + store iter 0 into buf 0
        {
            const int n0 = nbeg;
#pragma unroll
            for (int r = 0; r < 4; r++) {
                const int row = lrow + r * 16;
                As[0][lnn * 68 + row] = Ab[(size_t)row * NN + n0 + lnn];
            }
#pragma unroll
            for (int r = 0; r < 2; r++) {
                const int row = lrow + r * 16;
                Xs[0][lnn * 36 + row] = xb[(size_t)(c0 + row) * NN + n0 + lnn];
            }
        }

        for (int it = 0; it < 16; it++) {
            float aR[4], xR[2];
            const bool more = (it + 1 < 16);
            if (more) {
                const int n0 = nbeg + (it + 1) * 16;
#pragma unroll
                for (int r = 0; r < 4; r++)
                    aR[r] = Ab[(size_t)(lrow + r * 16) * NN + n0 + lnn];
#pragma unroll
                for (int r = 0; r < 2; r++)
                    xR[r] = xb[(size_t)(c0 + lrow + r * 16) * NN + n0 + lnn];
            }
            __syncthreads();
            const float* Ac = As[it & 1];
            const float* Xc = Xs[it & 1];
#pragma unroll
            for (int nn = 0; nn < 16; nn++) {
                const ulonglong2 ap = *reinterpret_cast<const ulonglong2*>(&Ac[nn * 68 + tk * 4]);
                const float2 xv = *reinterpret_cast<const float2*>(&Xc[nn * 36 + tc * 2]);
                const ull xd0 = pack2(xv.x, xv.x);
                const ull xd1 = pack2(xv.y, xv.y);
                acc[0][0] = fma2(ap.x, xd0, acc[0][0]);
                acc[0][1] = fma2(ap.x, xd1, acc[0][1]);
                acc[1][0] = fma2(ap.y, xd0, acc[1][0]);
                acc[1][1] = fma2(ap.y, xd1, acc[1][1]);
            }
            if (more) {
                float* An = As[(it + 1) & 1];
                float* Xn = Xs[(it + 1) & 1];
#pragma unroll
                for (int r = 0; r < 4; r++)
                    An[lnn * 68 + lrow + r * 16] = aR[r];
#pragma unroll
                for (int r = 0; r < 2; r++)
                    Xn[lnn * 36 + lrow + r * 16] = xR[r];
            }
        }

        float* P = g_part + ((size_t)ns * BB + b) * KK * CC;
#pragma unroll
        for (int kp = 0; kp < 2; kp++)
#pragma unroll
            for (int cj = 0; cj < 2; cj++) {
                const float2 v = unpack2(acc[kp][cj]);
                const int kg = tk * 4 + kp * 2;
                const int cg = c0 + tc * 2 + cj;
                P[(size_t)kg * CC + cg] = v.x;
                P[(size_t)(kg + 1) * CC + cg] = v.y;
            }
    }
    grid_bar(g_cntB, &g_masterB, &g_genB, GRID_B / 4, blk);

    // ---- Phase 2: epilogue (proven R15 k4 body), blocks 0..127 ----
    if (blk < 128) {
        float* redw = (float*)As;        // reuse smem
        float* red = redw + 2;
        float* rfs = red + 8;

        const int h = tid >> 7;    // half 0/1
        const int ht = tid & 127;
        const int r = blk * 2 + h; // 0..255
        const int b = r >> 6, k = r & 63;

        // issue ALL independent loads first (max MLP)
        float wv = 0.f;
        if (ht < 32) wv = g_wpart[(ht * BB + b) * KK + k];
        const int c = ht * 4;
        const size_t base = (size_t)b * KK * CC + (size_t)k * CC + c;
        float4 p0 = *reinterpret_cast<const float4*>(&g_part[(size_t)0 * BB * KK * CC + base]);
        float4 p1 = *reinterpret_cast<const float4*>(&g_part[(size_t)1 * BB * KK * CC + base]);
        float4 p2 = *reinterpret_cast<const float4*>(&g_part[(size_t)2 * BB * KK * CC + base]);
        float4 p3 = *reinterpret_cast<const float4*>(&g_part[(size_t)3 * BB * KK * CC + base]);
        const float4 a = *reinterpret_cast<const float4*>(&anchor[k * CC + c]);
        const float4 iv = *reinterpret_cast<const float4*>(&g_inv[k * CC + c]);

        if (ht < 32) {
#pragma unroll
            for (int o = 16; o > 0; o >>= 1) wv += __shfl_xor_sync(0xffffffffu, wv, o);
            if (ht == 0) redw[h] = wv;
        }
        __syncthreads();
        const float w = redw[h];
        const float invden = 1.f / (w + 1e-7f);

        float4 s;
        s.x = (p0.x + p1.x) + (p2.x + p3.x);
        s.y = (p0.y + p1.y) + (p2.y + p3.y);
        s.z = (p0.z + p1.z) + (p2.z + p3.z);
        s.w = (p0.w + p1.w) + (p2.w + p3.w);
        float4 v;
        v.x = (s.x - w * a.x) * iv.x * invden;
        v.y = (s.y - w * a.y) * iv.y * invden;
        v.z = (s.z - w * a.z) * iv.z * invden;
        v.w = (s.w - w * a.w) * iv.w * invden;

        float ss = v.x * v.x + v.y * v.y + v.z * v.z + v.w * v.w;
#pragma unroll
        for (int o = 16; o > 0; o >>= 1) ss += __shfl_xor_sync(0xffffffffu, ss, o);
        if ((ht & 31) == 0) red[h * 4 + (ht >> 5)] = ss;
        __syncthreads();
        if (ht == 0) {
            const float sumsq = red[h * 4] + red[h * 4 + 1] + red[h * 4 + 2] + red[h * 4 + 3];
            rfs[h] = 0.125f / fmaxf(sqrtf(sumsq), 1e-12f);  // row norm * 1/sqrt(K)
        }
        __syncthreads();
        const float rf = rfs[h];
        float4 o4;
        o4.x = v.x * rf; o4.y = v.y * rf; o4.z = v.z * rf; o4.w = v.w * rf;
        *reinterpret_cast<float4*>(&nodes_out[((size_t)b * KK + k) * CC + c]) = o4;
    }
}

// ------------------------------------------------------------------
extern "C" void kernel_launch(void* const* d_in, const int* in_sizes, int n_in,
                              void* d_out, int out_size) {
    (void)in_sizes; (void)n_in; (void)out_size;
    const float* x = (const float*)d_in[0];       // (4,512,32,32)
    const float* anchor = (const float*)d_in[1];  // (64,512)
    const float* sp = (const float*)d_in[2];      // (64,512)
    float* out = (float*)d_out;
    float* nodes_out = out;                        // B*K*C (viewed (B,C,K))
    float* soft_out = out + (size_t)BB * KK * CC;  // B*K*N

    kernelA<<<GRID_A, 256>>>(x, anchor, sp, soft_out);
    kernelB<<<GRID_B, 256>>>(x, anchor, soft_out, nodes_out);
}